// round 16
// baseline (speedup 1.0000x reference)
#include <cuda_runtime.h>

#define Bb 32
#define Nn 128
#define Dd 64
#define Ee 5
#define T_ITERS 6
#define GRID 128
#define THREADS 512
#define ROWS 32
#define JS 4
#define JT 32

// ---- smem float offsets ----
// staged each iteration (overlaid by phase 2):
#define OFF_WR   0        // 8192
#define OFF_WZ   8192     // 8192
#define OFF_WE   16384    // 20480 (ends 36864)
// phase-2 overlay:
#define OFF_MSG  0        // 32*320
#define OFF_SSC  10240    // 128*180 ([i][e][j], e-stride 36) = 23040
#define OFF_SROW 33280    // 640  (e^-row)
#define OFF_SCOL 33920    // 160  (e^-colba)
#define OFF_MASKB 34080   // 128 uint bitmask words (ends 34208 < 36864)
// persistent (never overlaid):
#define OFF_WH   36864    // 8192 (staged once at t=0)
#define OFF_WA   45056    // 640  (staged once at t=0)
#define OFF_SA   45696    // 32*68 merged
#define OFF_SP   47872    // 32*68 prop (persists across iterations)
#define OFF_SH2  50048    // 32*68 r*prop
#define OFF_SCR0 52224    // 2048 transposed u64 scratch
#define OFF_SCR1 54784    // 2048
#define SMEM_FLOATS 57344

__device__ float g_rowg[Bb*Nn*Ee];
__device__ float g_colba[Bb*Nn*Ee];
__device__ float g_part[2*JS][Bb*Nn][Dd];   // js*2 + j-half

typedef unsigned long long u64;

__device__ __forceinline__ u64 pack2(float a, float b) {
    u64 r; asm("mov.b64 %0, {%1,%2};" : "=l"(r) : "f"(a), "f"(b)); return r;
}
__device__ __forceinline__ void unpack2(u64 v, float& a, float& b) {
    float x, y; asm("mov.b64 {%0,%1}, %2;" : "=f"(x), "=f"(y) : "l"(v));
    a = x; b = y;
}
__device__ __forceinline__ u64 fma2(u64 a, u64 b, u64 c) {
    u64 d; asm("fma.rn.f32x2 %0, %1, %2, %3;" : "=l"(d) : "l"(a), "l"(b), "l"(c)); return d;
}
__device__ __forceinline__ u64 add2(u64 a, u64 b) {
    u64 d; asm("add.rn.f32x2 %0, %1, %2;" : "=l"(d) : "l"(a), "l"(b)); return d;
}
__device__ __forceinline__ float sigf(float x) {
    return __fdividef(1.0f, 1.0f + __expf(-x));
}
__device__ __forceinline__ float tanhff(float x) {
    return fmaf(2.0f, sigf(2.0f * x), -1.0f);
}
__device__ __forceinline__ unsigned cvta_smem(const void* p) {
    return (unsigned)__cvta_generic_to_shared(p);
}
__device__ __forceinline__ void cpa16(unsigned dst, const void* src) {
    asm volatile("cp.async.ca.shared.global [%0], [%1], 16;" :: "r"(dst), "l"(src));
}
#define CP_COMMIT  asm volatile("cp.async.commit_group;" ::: "memory")
#define CP_WAIT(n) asm volatile("cp.async.wait_group %0;" :: "n"(n) : "memory")

__device__ __forceinline__ void cluster_bar() {
    asm volatile("barrier.cluster.arrive.aligned;" ::: "memory");
    asm volatile("barrier.cluster.wait.aligned;" ::: "memory");
}

// transposed scratch: component-major, consecutive slots contiguous (2 wf/op)
__device__ __forceinline__ void scr_w(float* sm, int base, int slot, const u64 a[4][2]) {
#pragma unroll
    for (int r = 0; r < 4; r++) {
        *(u64*)&sm[base + (r*2+0)*256 + slot*2] = a[r][0];
        *(u64*)&sm[base + (r*2+1)*256 + slot*2] = a[r][1];
    }
}
__device__ __forceinline__ void scr_a(float* sm, int base, int slot, u64 a[4][2]) {
#pragma unroll
    for (int r = 0; r < 4; r++) {
        a[r][0] = add2(a[r][0], *(const u64*)&sm[base + (r*2+0)*256 + slot*2]);
        a[r][1] = add2(a[r][1], *(const u64*)&sm[base + (r*2+1)*256 + slot*2]);
    }
}
__device__ __forceinline__ void scr_r(float* sm, int base, int slot, u64 a[4][2]) {
#pragma unroll
    for (int r = 0; r < 4; r++) {
        a[r][0] = *(const u64*)&sm[base + (r*2+0)*256 + slot*2];
        a[r][1] = *(const u64*)&sm[base + (r*2+1)*256 + slot*2];
    }
}

__device__ __forceinline__ void gate_q2(const float* sm, int wb1, int wb2,
                                        int abase, int koff, int kg, int rg, int f0,
                                        u64 ar[4][2], u64 az[4][2]) {
#pragma unroll 2
    for (int s4 = 0; s4 < 32; s4 += 4) {
        float av[4][4];
#pragma unroll
        for (int r = 0; r < 4; r++) {
            float4 tv = *(const float4*)&sm[abase + (rg*4+r)*68 + koff + s4];
            av[r][0]=tv.x; av[r][1]=tv.y; av[r][2]=tv.z; av[r][3]=tv.w;
        }
#pragma unroll
        for (int u = 0; u < 4; u++) {
            int k = kg + s4 + u;
            float4 w1 = *(const float4*)&sm[wb1 + k*64 + f0];
            float4 w2 = *(const float4*)&sm[wb2 + k*64 + f0];
            u64 a01 = pack2(w1.x,w1.y), a23 = pack2(w1.z,w1.w);
            u64 b01 = pack2(w2.x,w2.y), b23 = pack2(w2.z,w2.w);
#pragma unroll
            for (int r = 0; r < 4; r++) {
                u64 aa = pack2(av[r][u], av[r][u]);
                ar[r][0] = fma2(aa, a01, ar[r][0]);
                ar[r][1] = fma2(aa, a23, ar[r][1]);
                az[r][0] = fma2(aa, b01, az[r][0]);
                az[r][1] = fma2(aa, b23, az[r][1]);
            }
        }
    }
}

__device__ __forceinline__ void gate_q1(const float* sm, int wb,
                                        int abase, int koff, int kg, int rg, int f0,
                                        u64 ah[4][2]) {
#pragma unroll 2
    for (int s4 = 0; s4 < 32; s4 += 4) {
        float av[4][4];
#pragma unroll
        for (int r = 0; r < 4; r++) {
            float4 tv = *(const float4*)&sm[abase + (rg*4+r)*68 + koff + s4];
            av[r][0]=tv.x; av[r][1]=tv.y; av[r][2]=tv.z; av[r][3]=tv.w;
        }
#pragma unroll
        for (int u = 0; u < 4; u++) {
            int k = kg + s4 + u;
            float4 w1 = *(const float4*)&sm[wb + k*64 + f0];
            u64 a01 = pack2(w1.x,w1.y), a23 = pack2(w1.z,w1.w);
#pragma unroll
            for (int r = 0; r < 4; r++) {
                u64 aa = pack2(av[r][u], av[r][u]);
                ah[r][0] = fma2(aa, a01, ah[r][0]);
                ah[r][1] = fma2(aa, a23, ah[r][1]);
            }
        }
    }
}

template<int NE, int EB>
__device__ __forceinline__ void msg_core(const float* sm, int rg, int f0, int dbase,
                                         u64 m[3][4][2]) {
#pragma unroll 2
    for (int d4 = 0; d4 < 32; d4 += 4) {
        float av[4][4];
#pragma unroll
        for (int r = 0; r < 4; r++) {
            float4 tv = *(const float4*)&sm[OFF_SP + (rg*4+r)*68 + dbase + d4];
            av[r][0]=tv.x; av[r][1]=tv.y; av[r][2]=tv.z; av[r][3]=tv.w;
        }
#pragma unroll
        for (int u = 0; u < 4; u++) {
            int d = dbase + d4 + u;
#pragma unroll
            for (int e = 0; e < NE; e++) {
                float4 w = *(const float4*)&sm[OFF_WE + (EB+e)*4096 + d*64 + f0];
                u64 w01 = pack2(w.x,w.y), w23 = pack2(w.z,w.w);
#pragma unroll
                for (int r = 0; r < 4; r++) {
                    u64 aa = pack2(av[r][u], av[r][u]);
                    m[e][r][0] = fma2(aa, w01, m[e][r][0]);
                    m[e][r][1] = fma2(aa, w23, m[e][r][1]);
                }
            }
        }
    }
}

// msg writer: split-half layout — (row,e) row is [halfA d(8k..8k+3)][halfB d(8k+4..8k+7)]
template<int NE, int EB>
__device__ __forceinline__ void msg_out(float* sm, int rg, int f0, int fg, int r0,
                                        const float* __restrict__ ba, u64 m[3][4][2]) {
    const int moff = (fg & 1)*32 + (fg >> 1)*4;
#pragma unroll
    for (int e = 0; e < NE; e++) {
        float bav = __ldg(&ba[EB+e]);
#pragma unroll
        for (int r = 0; r < 4; r++) {
            float v0,v1,v2,v3;
            unpack2(m[e][r][0], v0, v1); unpack2(m[e][r][1], v2, v3);
            int row = rg*4 + r;
            *(float4*)&sm[OFF_MSG + row*320 + (EB+e)*64 + moff] = make_float4(v0,v1,v2,v3);
            const float* wa = &sm[OFF_WA + (EB+e)*128 + f0];
            float rowp = v0*wa[0]; rowp = fmaf(v1,wa[1],rowp);
            rowp = fmaf(v2,wa[2],rowp); rowp = fmaf(v3,wa[3],rowp);
            float colp = v0*wa[64]; colp = fmaf(v1,wa[65],colp);
            colp = fmaf(v2,wa[66],colp); colp = fmaf(v3,wa[67],colp);
#pragma unroll
            for (int o = 8; o > 0; o >>= 1) {
                rowp += __shfl_down_sync(0xffffffffu, rowp, o, 16);
                colp += __shfl_down_sync(0xffffffffu, colp, o, 16);
            }
            if (fg == 0) {
                g_rowg[(r0+row)*5 + EB+e]  = rowp;
                g_colba[(r0+row)*5 + EB+e] = colp + bav;
            }
        }
    }
}

extern "C" __global__ void __cluster_dims__(4, 1, 1) __launch_bounds__(THREADS)
grrn(const float* __restrict__ inputs, const int* __restrict__ mask,
     const float* __restrict__ We, const float* __restrict__ be,
     const float* __restrict__ Wa, const float* __restrict__ ba,
     const float* __restrict__ Wr, const float* __restrict__ br,
     const float* __restrict__ Wz, const float* __restrict__ bz,
     const float* __restrict__ Wh, const float* __restrict__ bh,
     float* __restrict__ out)
{
    extern __shared__ float sm[];
    const int tid  = threadIdx.x;
    const int blk  = blockIdx.x;
    const int r0   = blk * ROWS;
    const int b    = blk >> 2;
    const int js   = blk & 3;
    const int j0   = js * JT;
    const int fg   = tid & 15;
    const int f0   = fg * 4;
    const int rg   = (tid >> 4) & 7;
    const int ks   = tid >> 7;
    const int slot = tid & 127;
    const unsigned sb = cvta_smem(sm);

    for (int t = 0; t < T_ITERS; t++) {
        if (t == 0) {
            // stage WE + persistent WH, WA (one group)
            for (int i = tid; i < 5120; i += THREADS)
                cpa16(sb + OFF_WE*4 + i*16, We + 4*i);
            for (int i = tid; i < 2048; i += THREADS)
                cpa16(sb + OFF_WH*4 + i*16, Wh + 4*i);
            if (tid < 160) cpa16(sb + OFF_WA*4 + tid*16, Wa + 4*tid);
            CP_COMMIT;
            int rr = tid >> 4;
            float4 p = *(const float4*)&inputs[(size_t)(r0 + rr)*Dd + f0];
            *(float4*)&sm[OFF_SP + rr*68 + f0] = p;
            CP_WAIT(0);
            __syncthreads();
        } else {
            // stage G1=(Wr,Wz), G2=(We); Wh/Wa persistent
            for (int i = tid; i < 2048; i += THREADS) {
                cpa16(sb + OFF_WR*4 + i*16, Wr + 4*i);
                cpa16(sb + OFF_WZ*4 + i*16, Wz + 4*i);
            }
            CP_COMMIT;
            for (int i = tid; i < 5120; i += THREADS)
                cpa16(sb + OFF_WE*4 + i*16, We + 4*i);
            CP_COMMIT;

            // merged = sum of 8 partials (4 js siblings x 2 j-halves)
            {
                int rr = tid >> 4;
                float4 msum = make_float4(0.f,0.f,0.f,0.f);
#pragma unroll
                for (int p = 0; p < 2*JS; p++) {
                    float4 a = __ldcg((const float4*)&g_part[p][r0 + rr][f0]);
                    msum.x += a.x; msum.y += a.y; msum.z += a.z; msum.w += a.w;
                }
                *(float4*)&sm[OFF_SA + rr*68 + f0] = msum;
            }
            CP_WAIT(1);          // Wr, Wz staged
            __syncthreads();

            // ---- rz gates: k-quarter per ks ----
            u64 ar[4][2], az[4][2];
            if (ks == 0) {
                float4 brv = __ldg((const float4*)&br[f0]);
                float4 bzv = __ldg((const float4*)&bz[f0]);
#pragma unroll
                for (int r = 0; r < 4; r++) {
                    ar[r][0] = pack2(brv.x,brv.y); ar[r][1] = pack2(brv.z,brv.w);
                    az[r][0] = pack2(bzv.x,bzv.y); az[r][1] = pack2(bzv.z,bzv.w);
                }
            } else {
#pragma unroll
                for (int r = 0; r < 4; r++)
                    ar[r][0]=ar[r][1]=az[r][0]=az[r][1]=0ull;
            }
            {
                const int abase = (ks < 2) ? OFF_SA : OFF_SP;
                const int koff  = (ks & 1) * 32;
                const int kg    = ks * 32;
                gate_q2(sm, OFF_WR, OFF_WZ, abase, koff, kg, rg, f0, ar, az);
            }
            if (ks == 2) scr_w(sm, OFF_SCR0, slot, ar);
            if (ks == 3) scr_w(sm, OFF_SCR1, slot, az);
            __syncthreads();
            if (ks == 0) scr_a(sm, OFF_SCR0, slot, ar);
            if (ks == 1) scr_a(sm, OFF_SCR1, slot, az);
            __syncthreads();
            if (ks == 3) scr_w(sm, OFF_SCR0, slot, ar);
            if (ks == 2) scr_w(sm, OFF_SCR1, slot, az);
            __syncthreads();
            if (ks == 0) scr_a(sm, OFF_SCR0, slot, ar);
            if (ks == 1) scr_a(sm, OFF_SCR1, slot, az);
            __syncthreads();
            if (ks == 1) scr_w(sm, OFF_SCR0, slot, ar);
            if (ks == 0) scr_w(sm, OFF_SCR1, slot, az);
            __syncthreads();

            float zq[4][4];
            if (ks == 0) {
                scr_a(sm, OFF_SCR0, slot, ar);
#pragma unroll
                for (int r = 0; r < 4; r++) {
                    float x0,x1,x2,x3;
                    unpack2(ar[r][0], x0, x1); unpack2(ar[r][1], x2, x3);
                    int row = rg*4 + r;
                    const float* pp = &sm[OFF_SP + row*68 + f0];
                    float* sh = &sm[OFF_SH2 + row*68 + f0];
                    sh[0] = sigf(x0)*pp[0]; sh[1] = sigf(x1)*pp[1];
                    sh[2] = sigf(x2)*pp[2]; sh[3] = sigf(x3)*pp[3];
                }
            }
            if (ks == 1) {
                scr_a(sm, OFF_SCR1, slot, az);
#pragma unroll
                for (int r = 0; r < 4; r++) {
                    float x0,x1,x2,x3;
                    unpack2(az[r][0], x0, x1); unpack2(az[r][1], x2, x3);
                    zq[r][0]=sigf(x0); zq[r][1]=sigf(x1);
                    zq[r][2]=sigf(x2); zq[r][3]=sigf(x3);
                }
            }
            __syncthreads();

            // ---- h gate (Wh persistent — no wait) ----
            u64 ah[4][2];
            if (ks == 0) {
                float4 bhv = __ldg((const float4*)&bh[f0]);
#pragma unroll
                for (int r = 0; r < 4; r++) {
                    ah[r][0] = pack2(bhv.x,bhv.y); ah[r][1] = pack2(bhv.z,bhv.w);
                }
            } else {
#pragma unroll
                for (int r = 0; r < 4; r++) ah[r][0]=ah[r][1]=0ull;
            }
            {
                const int hbase = (ks < 2) ? OFF_SA : OFF_SH2;
                const int koff  = (ks & 1) * 32;
                const int kg    = ks * 32;
                gate_q1(sm, OFF_WH, hbase, koff, kg, rg, f0, ah);
            }
            if (ks == 1) scr_w(sm, OFF_SCR0, slot, ah);
            if (ks == 2) scr_w(sm, OFF_SCR1, slot, ah);
            __syncthreads();
            if (ks == 0) { scr_a(sm, OFF_SCR0, slot, ah); scr_a(sm, OFF_SCR1, slot, ah); }
            __syncthreads();
            if (ks == 3) scr_w(sm, OFF_SCR0, slot, ah);
            if (ks == 1) {
                u64 zq8[4][2];
#pragma unroll
                for (int r = 0; r < 4; r++) {
                    zq8[r][0] = pack2(zq[r][0], zq[r][1]);
                    zq8[r][1] = pack2(zq[r][2], zq[r][3]);
                }
                scr_w(sm, OFF_SCR1, slot, zq8);
            }
            CP_WAIT(0);          // We staged
            __syncthreads();
            if (ks == 0) {
                scr_a(sm, OFF_SCR0, slot, ah);
                u64 zq8[4][2];
                scr_r(sm, OFF_SCR1, slot, zq8);
#pragma unroll
                for (int r = 0; r < 4; r++) {
                    float h0,h1,h2,h3;
                    unpack2(ah[r][0], h0, h1); unpack2(ah[r][1], h2, h3);
                    float z0,z1,z2,z3;
                    unpack2(zq8[r][0], z0, z1); unpack2(zq8[r][1], z2, z3);
                    int row = rg*4 + r;
                    float4 pv = *(const float4*)&sm[OFF_SP + row*68 + f0];
                    float4 np;
                    np.x = fmaf(z0, tanhff(h0) - pv.x, pv.x);
                    np.y = fmaf(z1, tanhff(h1) - pv.y, pv.y);
                    np.z = fmaf(z2, tanhff(h2) - pv.z, pv.z);
                    np.w = fmaf(z3, tanhff(h3) - pv.w, pv.w);
                    *(float4*)&sm[OFF_SP + row*68 + f0] = np;
                }
            }
            __syncthreads();
        }

        // ---- msg GEMM: (eg,dg) split ----
        u64 m[3][4][2];
        const int eg = ks >> 1;
        const int dbase = (ks & 1) * 32;
        if (eg == 0) {
            if ((ks & 1) == 0) {
#pragma unroll
                for (int e = 0; e < 3; e++) {
                    float4 bev = __ldg((const float4*)&be[e*64 + f0]);
#pragma unroll
                    for (int r = 0; r < 4; r++) {
                        m[e][r][0] = pack2(bev.x,bev.y); m[e][r][1] = pack2(bev.z,bev.w);
                    }
                }
            } else {
#pragma unroll
                for (int e = 0; e < 3; e++)
#pragma unroll
                    for (int r = 0; r < 4; r++) m[e][r][0]=m[e][r][1]=0ull;
            }
            msg_core<3,0>(sm, rg, f0, dbase, m);
        } else {
            if ((ks & 1) == 0) {
#pragma unroll
                for (int e = 0; e < 2; e++) {
                    float4 bev = __ldg((const float4*)&be[(3+e)*64 + f0]);
#pragma unroll
                    for (int r = 0; r < 4; r++) {
                        m[e][r][0] = pack2(bev.x,bev.y); m[e][r][1] = pack2(bev.z,bev.w);
                    }
                }
            } else {
#pragma unroll
                for (int e = 0; e < 2; e++)
#pragma unroll
                    for (int r = 0; r < 4; r++) m[e][r][0]=m[e][r][1]=0ull;
            }
            msg_core<2,3>(sm, rg, f0, dbase, m);
        }
        if (ks == 1) scr_w(sm, OFF_SCR0, slot, m[0]);
        if (ks == 3) scr_w(sm, OFF_SCR1, slot, m[0]);
        __syncthreads();
        if (ks == 0) scr_a(sm, OFF_SCR0, slot, m[0]);
        if (ks == 2) scr_a(sm, OFF_SCR1, slot, m[0]);
        __syncthreads();
        if (ks == 1) scr_w(sm, OFF_SCR0, slot, m[1]);
        if (ks == 3) scr_w(sm, OFF_SCR1, slot, m[1]);
        __syncthreads();
        if (ks == 0) scr_a(sm, OFF_SCR0, slot, m[1]);
        if (ks == 2) scr_a(sm, OFF_SCR1, slot, m[1]);
        __syncthreads();
        if (ks == 1) scr_w(sm, OFF_SCR0, slot, m[2]);
        __syncthreads();
        if (ks == 0) {
            scr_a(sm, OFF_SCR0, slot, m[2]);
            msg_out<3,0>(sm, rg, f0, fg, r0, ba, m);
        }
        if (ks == 2) msg_out<2,3>(sm, rg, f0, fg, r0, ba, m);
        cluster_bar();

        // ================= PHASE 2: scores + merged =================
        for (int i = tid; i < 640; i += THREADS)
            sm[OFF_SROW + i] = __expf(-__ldcg(&g_rowg[b*640 + i]));
        for (int i = tid; i < 160; i += THREADS)
            sm[OFF_SCOL + i] = __expf(-__ldcg(&g_colba[(b*Nn + j0)*5 + i]));
        if (tid < 128) {   // bit-pack mask: one uint per i row
            const int* mrow = &mask[(size_t)(b*Nn + tid)*Nn + j0];
            unsigned w = 0;
#pragma unroll
            for (int seg = 0; seg < 8; seg++) {
                int4 mv = __ldg((const int4*)&mrow[seg*4]);
                w |= (unsigned)(mv.x & 1) << (seg*4);
                w |= (unsigned)(mv.y & 1) << (seg*4+1);
                w |= (unsigned)(mv.z & 1) << (seg*4+2);
                w |= (unsigned)(mv.w & 1) << (seg*4+3);
            }
            ((unsigned*)&sm[OFF_MASKB])[tid] = w;
        }
        __syncthreads();

        // scores: sigmoid(row+col) = 1/(1 + e^-row * e^-col); 1 MUFU each.
        float* outB = out + (size_t)(t*Bb + b)*(Nn*Nn*Ee) + (size_t)j0*Ee;
#pragma unroll 2
        for (int p = 0; p < 10; p++) {
            int idx4 = p*512 + tid;
            int i = idx4 / 40;
            int posb = (idx4 - i*40) * 4;
            unsigned mw = ((const unsigned*)&sm[OFF_MASKB])[i];
            float4 ecol = *(const float4*)&sm[OFF_SCOL + posb];
            const float* ecp = (const float*)&ecol;
            float4 sv;
            float* svp = (float*)&sv;
#pragma unroll
            for (int u = 0; u < 4; u++) {
                int pos = posb + u;
                int j = (pos * 6554) >> 15;
                int e = pos - j*5;
                float er = sm[OFF_SROW + i*5 + e];
                float rec = __fdividef(1.0f, fmaf(er, ecp[u], 1.0f));
                float s = ((mw >> j) & 1u) ? rec : 0.0f;
                svp[u] = s;
                sm[OFF_SSC + i*180 + e*36 + j] = s;
            }
            *(float4*)&outB[(size_t)i*640 + posb] = sv;
        }

        if (t < T_ITERS - 1) {
            __syncthreads();
            const int td = tid & 7;
            const int ti = (tid >> 3) & 31;
            const int kh = tid >> 8;
            const int d0 = td * 8;
            u64 a2[4][4];
#pragma unroll
            for (int q = 0; q < 4; q++)
#pragma unroll
                for (int h = 0; h < 4; h++) a2[q][h] = 0ull;

#pragma unroll 1
            for (int jq = 0; jq < 4; jq++) {
                const int jbase = kh*16 + jq*4;
#pragma unroll
                for (int e = 0; e < 5; e++) {
                    float4 sq[4];
#pragma unroll
                    for (int q = 0; q < 4; q++)
                        sq[q] = *(const float4*)&sm[OFF_SSC + (ti*4+q)*180 + e*36 + jbase];
#pragma unroll
                    for (int jj = 0; jj < 4; jj++) {
                        const float* mr = &sm[OFF_MSG + (jbase+jj)*320 + e*64 + td*4];
                        float4 ma = *(const float4*)mr;
                        float4 mb = *(const float4*)(mr + 32);
                        u64 m0 = pack2(ma.x,ma.y), m1 = pack2(ma.z,ma.w);
                        u64 m2 = pack2(mb.x,mb.y), m3 = pack2(mb.z,mb.w);
#pragma unroll
                        for (int q = 0; q < 4; q++) {
                            float s = ((const float*)&sq[q])[jj];
                            u64 ss = pack2(s,s);
                            a2[q][0] = fma2(ss, m0, a2[q][0]);
                            a2[q][1] = fma2(ss, m1, a2[q][1]);
                            a2[q][2] = fma2(ss, m2, a2[q][2]);
                            a2[q][3] = fma2(ss, m3, a2[q][3]);
                        }
                    }
                }
            }
#pragma unroll
            for (int q = 0; q < 4; q++) {
                float v[8];
                unpack2(a2[q][0], v[0], v[1]); unpack2(a2[q][1], v[2], v[3]);
                unpack2(a2[q][2], v[4], v[5]); unpack2(a2[q][3], v[6], v[7]);
                float* dst = &g_part[js*2 + kh][b*Nn + ti*4 + q][d0];
                *(float4*)dst       = make_float4(v[0],v[1],v[2],v[3]);
                *(float4*)(dst + 4) = make_float4(v[4],v[5],v[6],v[7]);
            }
            cluster_bar();
        }
    }
}

extern "C" void kernel_launch(void* const* d_in, const int* in_sizes, int n_in,
                              void* d_out, int out_size) {
    const float* inputs = (const float*)d_in[0];
    const int*   mask   = (const int*)  d_in[1];
    const float* We     = (const float*)d_in[2];
    const float* be     = (const float*)d_in[3];
    const float* Wa     = (const float*)d_in[4];
    const float* ba     = (const float*)d_in[5];
    const float* Wr     = (const float*)d_in[6];
    const float* br     = (const float*)d_in[7];
    const float* Wz     = (const float*)d_in[8];
    const float* bz     = (const float*)d_in[9];
    const float* Wh     = (const float*)d_in[10];
    const float* bh     = (const float*)d_in[11];
    float* out = (float*)d_out;

    static int configured = 0;
    if (!configured) {
        cudaFuncSetAttribute(grrn, cudaFuncAttributeMaxDynamicSharedMemorySize,
                             SMEM_FLOATS * 4);
        configured = 1;
    }
    grrn<<<GRID, THREADS, SMEM_FLOATS * 4>>>(inputs, mask, We, be, Wa, ba,
                                             Wr, br, Wz, bz, Wh, bh, out);
}

// round 17
// speedup vs baseline: 1.0282x; 1.0282x over previous
#include <cuda_runtime.h>
#include <cuda_fp16.h>

#define Bb 32
#define Nn 128
#define Dd 64
#define Ee 5
#define T_ITERS 6
#define GRID 128
#define THREADS 512
#define ROWS 32
#define JS 4
#define JT 32

// ---- smem float offsets ----
// staged each iteration (overlaid by phase 2):
#define OFF_WR   0        // 8192
#define OFF_WZ   8192     // 8192
#define OFF_WE   16384    // 20480 (ends 36864)
// phase-2 overlay:
#define OFF_MSG  0        // 32*320
#define OFF_SSC  10240    // 128*180 ([i][e][j], e-stride 36) = 23040
#define OFF_SROW 33280    // 640  (e^-row)
#define OFF_SCOL 33920    // 160  (e^-colba)
#define OFF_MASKH 34080   // 4096 halves = 2048 floats (ends 36128 < 36864)
// persistent (never overlaid):
#define OFF_WH   36864    // 8192 (staged once at t=0)
#define OFF_WA   45056    // 640  (staged once at t=0)
#define OFF_SA   45696    // 32*68 merged
#define OFF_SP   47872    // 32*68 prop (persists across iterations)
#define OFF_SH2  50048    // 32*68 r*prop
#define OFF_SCR0 52224    // 2048 transposed u64 scratch
#define OFF_SCR1 54784    // 2048
#define SMEM_FLOATS 57344

__device__ float g_rowg[Bb*Nn*Ee];
__device__ float g_colba[Bb*Nn*Ee];
__device__ float g_part[2*JS][Bb*Nn][Dd];   // js*2 + j-half

typedef unsigned long long u64;

__device__ __forceinline__ u64 pack2(float a, float b) {
    u64 r; asm("mov.b64 %0, {%1,%2};" : "=l"(r) : "f"(a), "f"(b)); return r;
}
__device__ __forceinline__ void unpack2(u64 v, float& a, float& b) {
    float x, y; asm("mov.b64 {%0,%1}, %2;" : "=f"(x), "=f"(y) : "l"(v));
    a = x; b = y;
}
__device__ __forceinline__ u64 fma2(u64 a, u64 b, u64 c) {
    u64 d; asm("fma.rn.f32x2 %0, %1, %2, %3;" : "=l"(d) : "l"(a), "l"(b), "l"(c)); return d;
}
__device__ __forceinline__ u64 add2(u64 a, u64 b) {
    u64 d; asm("add.rn.f32x2 %0, %1, %2;" : "=l"(d) : "l"(a), "l"(b)); return d;
}
__device__ __forceinline__ float sigf(float x) {
    return __fdividef(1.0f, 1.0f + __expf(-x));
}
__device__ __forceinline__ float tanhff(float x) {
    return fmaf(2.0f, sigf(2.0f * x), -1.0f);
}
__device__ __forceinline__ unsigned cvta_smem(const void* p) {
    return (unsigned)__cvta_generic_to_shared(p);
}
__device__ __forceinline__ void cpa16(unsigned dst, const void* src) {
    asm volatile("cp.async.ca.shared.global [%0], [%1], 16;" :: "r"(dst), "l"(src));
}
#define CP_COMMIT  asm volatile("cp.async.commit_group;" ::: "memory")
#define CP_WAIT(n) asm volatile("cp.async.wait_group %0;" :: "n"(n) : "memory")

__device__ __forceinline__ void cluster_bar() {
    asm volatile("barrier.cluster.arrive.aligned;" ::: "memory");
    asm volatile("barrier.cluster.wait.aligned;" ::: "memory");
}

// transposed scratch: component-major, consecutive slots contiguous (2 wf/op)
__device__ __forceinline__ void scr_w(float* sm, int base, int slot, const u64 a[4][2]) {
#pragma unroll
    for (int r = 0; r < 4; r++) {
        *(u64*)&sm[base + (r*2+0)*256 + slot*2] = a[r][0];
        *(u64*)&sm[base + (r*2+1)*256 + slot*2] = a[r][1];
    }
}
__device__ __forceinline__ void scr_a(float* sm, int base, int slot, u64 a[4][2]) {
#pragma unroll
    for (int r = 0; r < 4; r++) {
        a[r][0] = add2(a[r][0], *(const u64*)&sm[base + (r*2+0)*256 + slot*2]);
        a[r][1] = add2(a[r][1], *(const u64*)&sm[base + (r*2+1)*256 + slot*2]);
    }
}
__device__ __forceinline__ void scr_r(float* sm, int base, int slot, u64 a[4][2]) {
#pragma unroll
    for (int r = 0; r < 4; r++) {
        a[r][0] = *(const u64*)&sm[base + (r*2+0)*256 + slot*2];
        a[r][1] = *(const u64*)&sm[base + (r*2+1)*256 + slot*2];
    }
}

__device__ __forceinline__ void gate_q2(const float* sm, int wb1, int wb2,
                                        int abase, int koff, int kg, int rg, int f0,
                                        u64 ar[4][2], u64 az[4][2]) {
#pragma unroll 2
    for (int s4 = 0; s4 < 32; s4 += 4) {
        float av[4][4];
#pragma unroll
        for (int r = 0; r < 4; r++) {
            float4 tv = *(const float4*)&sm[abase + (rg*4+r)*68 + koff + s4];
            av[r][0]=tv.x; av[r][1]=tv.y; av[r][2]=tv.z; av[r][3]=tv.w;
        }
#pragma unroll
        for (int u = 0; u < 4; u++) {
            int k = kg + s4 + u;
            float4 w1 = *(const float4*)&sm[wb1 + k*64 + f0];
            float4 w2 = *(const float4*)&sm[wb2 + k*64 + f0];
            u64 a01 = pack2(w1.x,w1.y), a23 = pack2(w1.z,w1.w);
            u64 b01 = pack2(w2.x,w2.y), b23 = pack2(w2.z,w2.w);
#pragma unroll
            for (int r = 0; r < 4; r++) {
                u64 aa = pack2(av[r][u], av[r][u]);
                ar[r][0] = fma2(aa, a01, ar[r][0]);
                ar[r][1] = fma2(aa, a23, ar[r][1]);
                az[r][0] = fma2(aa, b01, az[r][0]);
                az[r][1] = fma2(aa, b23, az[r][1]);
            }
        }
    }
}

__device__ __forceinline__ void gate_q1(const float* sm, int wb,
                                        int abase, int koff, int kg, int rg, int f0,
                                        u64 ah[4][2]) {
#pragma unroll 2
    for (int s4 = 0; s4 < 32; s4 += 4) {
        float av[4][4];
#pragma unroll
        for (int r = 0; r < 4; r++) {
            float4 tv = *(const float4*)&sm[abase + (rg*4+r)*68 + koff + s4];
            av[r][0]=tv.x; av[r][1]=tv.y; av[r][2]=tv.z; av[r][3]=tv.w;
        }
#pragma unroll
        for (int u = 0; u < 4; u++) {
            int k = kg + s4 + u;
            float4 w1 = *(const float4*)&sm[wb + k*64 + f0];
            u64 a01 = pack2(w1.x,w1.y), a23 = pack2(w1.z,w1.w);
#pragma unroll
            for (int r = 0; r < 4; r++) {
                u64 aa = pack2(av[r][u], av[r][u]);
                ah[r][0] = fma2(aa, a01, ah[r][0]);
                ah[r][1] = fma2(aa, a23, ah[r][1]);
            }
        }
    }
}

template<int NE, int EB>
__device__ __forceinline__ void msg_core(const float* sm, int rg, int f0, int dbase,
                                         u64 m[3][4][2]) {
#pragma unroll 2
    for (int d4 = 0; d4 < 32; d4 += 4) {
        float av[4][4];
#pragma unroll
        for (int r = 0; r < 4; r++) {
            float4 tv = *(const float4*)&sm[OFF_SP + (rg*4+r)*68 + dbase + d4];
            av[r][0]=tv.x; av[r][1]=tv.y; av[r][2]=tv.z; av[r][3]=tv.w;
        }
#pragma unroll
        for (int u = 0; u < 4; u++) {
            int d = dbase + d4 + u;
#pragma unroll
            for (int e = 0; e < NE; e++) {
                float4 w = *(const float4*)&sm[OFF_WE + (EB+e)*4096 + d*64 + f0];
                u64 w01 = pack2(w.x,w.y), w23 = pack2(w.z,w.w);
#pragma unroll
                for (int r = 0; r < 4; r++) {
                    u64 aa = pack2(av[r][u], av[r][u]);
                    m[e][r][0] = fma2(aa, w01, m[e][r][0]);
                    m[e][r][1] = fma2(aa, w23, m[e][r][1]);
                }
            }
        }
    }
}

// msg writer: split-half layout — (row,e) row is [halfA d(8k..8k+3)][halfB d(8k+4..8k+7)]
template<int NE, int EB>
__device__ __forceinline__ void msg_out(float* sm, int rg, int f0, int fg, int r0,
                                        const float* __restrict__ ba, u64 m[3][4][2]) {
    const int moff = (fg & 1)*32 + (fg >> 1)*4;
#pragma unroll
    for (int e = 0; e < NE; e++) {
        float bav = __ldg(&ba[EB+e]);
#pragma unroll
        for (int r = 0; r < 4; r++) {
            float v0,v1,v2,v3;
            unpack2(m[e][r][0], v0, v1); unpack2(m[e][r][1], v2, v3);
            int row = rg*4 + r;
            *(float4*)&sm[OFF_MSG + row*320 + (EB+e)*64 + moff] = make_float4(v0,v1,v2,v3);
            const float* wa = &sm[OFF_WA + (EB+e)*128 + f0];
            float rowp = v0*wa[0]; rowp = fmaf(v1,wa[1],rowp);
            rowp = fmaf(v2,wa[2],rowp); rowp = fmaf(v3,wa[3],rowp);
            float colp = v0*wa[64]; colp = fmaf(v1,wa[65],colp);
            colp = fmaf(v2,wa[66],colp); colp = fmaf(v3,wa[67],colp);
#pragma unroll
            for (int o = 8; o > 0; o >>= 1) {
                rowp += __shfl_down_sync(0xffffffffu, rowp, o, 16);
                colp += __shfl_down_sync(0xffffffffu, colp, o, 16);
            }
            if (fg == 0) {
                g_rowg[(r0+row)*5 + EB+e]  = rowp;
                g_colba[(r0+row)*5 + EB+e] = colp + bav;
            }
        }
    }
}

extern "C" __global__ void __cluster_dims__(4, 1, 1) __launch_bounds__(THREADS)
grrn(const float* __restrict__ inputs, const int* __restrict__ mask,
     const float* __restrict__ We, const float* __restrict__ be,
     const float* __restrict__ Wa, const float* __restrict__ ba,
     const float* __restrict__ Wr, const float* __restrict__ br,
     const float* __restrict__ Wz, const float* __restrict__ bz,
     const float* __restrict__ Wh, const float* __restrict__ bh,
     float* __restrict__ out)
{
    extern __shared__ float sm[];
    const int tid  = threadIdx.x;
    const int blk  = blockIdx.x;
    const int r0   = blk * ROWS;
    const int b    = blk >> 2;
    const int js   = blk & 3;
    const int j0   = js * JT;
    const int fg   = tid & 15;
    const int f0   = fg * 4;
    const int rg   = (tid >> 4) & 7;
    const int ks   = tid >> 7;
    const int slot = tid & 127;
    const unsigned sb = cvta_smem(sm);

    for (int t = 0; t < T_ITERS; t++) {
        if (t == 0) {
            // stage WE + persistent WH, WA (one group)
            for (int i = tid; i < 5120; i += THREADS)
                cpa16(sb + OFF_WE*4 + i*16, We + 4*i);
            for (int i = tid; i < 2048; i += THREADS)
                cpa16(sb + OFF_WH*4 + i*16, Wh + 4*i);
            if (tid < 160) cpa16(sb + OFF_WA*4 + tid*16, Wa + 4*tid);
            CP_COMMIT;
            int rr = tid >> 4;
            float4 p = *(const float4*)&inputs[(size_t)(r0 + rr)*Dd + f0];
            *(float4*)&sm[OFF_SP + rr*68 + f0] = p;
            CP_WAIT(0);
            __syncthreads();
        } else {
            // stage G1=(Wr,Wz), G2=(We); Wh/Wa persistent
            for (int i = tid; i < 2048; i += THREADS) {
                cpa16(sb + OFF_WR*4 + i*16, Wr + 4*i);
                cpa16(sb + OFF_WZ*4 + i*16, Wz + 4*i);
            }
            CP_COMMIT;
            for (int i = tid; i < 5120; i += THREADS)
                cpa16(sb + OFF_WE*4 + i*16, We + 4*i);
            CP_COMMIT;

            // merged = sum of 8 partials (4 js siblings x 2 j-halves)
            {
                int rr = tid >> 4;
                float4 msum = make_float4(0.f,0.f,0.f,0.f);
#pragma unroll
                for (int p = 0; p < 2*JS; p++) {
                    float4 a = __ldcg((const float4*)&g_part[p][r0 + rr][f0]);
                    msum.x += a.x; msum.y += a.y; msum.z += a.z; msum.w += a.w;
                }
                *(float4*)&sm[OFF_SA + rr*68 + f0] = msum;
            }
            CP_WAIT(1);          // Wr, Wz staged
            __syncthreads();

            // ---- rz gates: k-quarter per ks ----
            u64 ar[4][2], az[4][2];
            if (ks == 0) {
                float4 brv = __ldg((const float4*)&br[f0]);
                float4 bzv = __ldg((const float4*)&bz[f0]);
#pragma unroll
                for (int r = 0; r < 4; r++) {
                    ar[r][0] = pack2(brv.x,brv.y); ar[r][1] = pack2(brv.z,brv.w);
                    az[r][0] = pack2(bzv.x,bzv.y); az[r][1] = pack2(bzv.z,bzv.w);
                }
            } else {
#pragma unroll
                for (int r = 0; r < 4; r++)
                    ar[r][0]=ar[r][1]=az[r][0]=az[r][1]=0ull;
            }
            {
                const int abase = (ks < 2) ? OFF_SA : OFF_SP;
                const int koff  = (ks & 1) * 32;
                const int kg    = ks * 32;
                gate_q2(sm, OFF_WR, OFF_WZ, abase, koff, kg, rg, f0, ar, az);
            }
            if (ks == 2) scr_w(sm, OFF_SCR0, slot, ar);
            if (ks == 3) scr_w(sm, OFF_SCR1, slot, az);
            __syncthreads();
            if (ks == 0) scr_a(sm, OFF_SCR0, slot, ar);
            if (ks == 1) scr_a(sm, OFF_SCR1, slot, az);
            __syncthreads();
            if (ks == 3) scr_w(sm, OFF_SCR0, slot, ar);
            if (ks == 2) scr_w(sm, OFF_SCR1, slot, az);
            __syncthreads();
            if (ks == 0) scr_a(sm, OFF_SCR0, slot, ar);
            if (ks == 1) scr_a(sm, OFF_SCR1, slot, az);
            __syncthreads();
            if (ks == 1) scr_w(sm, OFF_SCR0, slot, ar);
            if (ks == 0) scr_w(sm, OFF_SCR1, slot, az);
            __syncthreads();

            float zq[4][4];
            if (ks == 0) {
                scr_a(sm, OFF_SCR0, slot, ar);
#pragma unroll
                for (int r = 0; r < 4; r++) {
                    float x0,x1,x2,x3;
                    unpack2(ar[r][0], x0, x1); unpack2(ar[r][1], x2, x3);
                    int row = rg*4 + r;
                    const float* pp = &sm[OFF_SP + row*68 + f0];
                    float* sh = &sm[OFF_SH2 + row*68 + f0];
                    sh[0] = sigf(x0)*pp[0]; sh[1] = sigf(x1)*pp[1];
                    sh[2] = sigf(x2)*pp[2]; sh[3] = sigf(x3)*pp[3];
                }
            }
            if (ks == 1) {
                scr_a(sm, OFF_SCR1, slot, az);
#pragma unroll
                for (int r = 0; r < 4; r++) {
                    float x0,x1,x2,x3;
                    unpack2(az[r][0], x0, x1); unpack2(az[r][1], x2, x3);
                    zq[r][0]=sigf(x0); zq[r][1]=sigf(x1);
                    zq[r][2]=sigf(x2); zq[r][3]=sigf(x3);
                }
            }
            __syncthreads();

            // ---- h gate (Wh persistent — no wait) ----
            u64 ah[4][2];
            if (ks == 0) {
                float4 bhv = __ldg((const float4*)&bh[f0]);
#pragma unroll
                for (int r = 0; r < 4; r++) {
                    ah[r][0] = pack2(bhv.x,bhv.y); ah[r][1] = pack2(bhv.z,bhv.w);
                }
            } else {
#pragma unroll
                for (int r = 0; r < 4; r++) ah[r][0]=ah[r][1]=0ull;
            }
            {
                const int hbase = (ks < 2) ? OFF_SA : OFF_SH2;
                const int koff  = (ks & 1) * 32;
                const int kg    = ks * 32;
                gate_q1(sm, OFF_WH, hbase, koff, kg, rg, f0, ah);
            }
            if (ks == 1) scr_w(sm, OFF_SCR0, slot, ah);
            if (ks == 2) scr_w(sm, OFF_SCR1, slot, ah);
            __syncthreads();
            if (ks == 0) { scr_a(sm, OFF_SCR0, slot, ah); scr_a(sm, OFF_SCR1, slot, ah); }
            __syncthreads();
            if (ks == 3) scr_w(sm, OFF_SCR0, slot, ah);
            if (ks == 1) {
                u64 zq8[4][2];
#pragma unroll
                for (int r = 0; r < 4; r++) {
                    zq8[r][0] = pack2(zq[r][0], zq[r][1]);
                    zq8[r][1] = pack2(zq[r][2], zq[r][3]);
                }
                scr_w(sm, OFF_SCR1, slot, zq8);
            }
            CP_WAIT(0);          // We staged
            __syncthreads();
            if (ks == 0) {
                scr_a(sm, OFF_SCR0, slot, ah);
                u64 zq8[4][2];
                scr_r(sm, OFF_SCR1, slot, zq8);
#pragma unroll
                for (int r = 0; r < 4; r++) {
                    float h0,h1,h2,h3;
                    unpack2(ah[r][0], h0, h1); unpack2(ah[r][1], h2, h3);
                    float z0,z1,z2,z3;
                    unpack2(zq8[r][0], z0, z1); unpack2(zq8[r][1], z2, z3);
                    int row = rg*4 + r;
                    float4 pv = *(const float4*)&sm[OFF_SP + row*68 + f0];
                    float4 np;
                    np.x = fmaf(z0, tanhff(h0) - pv.x, pv.x);
                    np.y = fmaf(z1, tanhff(h1) - pv.y, pv.y);
                    np.z = fmaf(z2, tanhff(h2) - pv.z, pv.z);
                    np.w = fmaf(z3, tanhff(h3) - pv.w, pv.w);
                    *(float4*)&sm[OFF_SP + row*68 + f0] = np;
                }
            }
            __syncthreads();
        }

        // ---- msg GEMM: (eg,dg) split ----
        u64 m[3][4][2];
        const int eg = ks >> 1;
        const int dbase = (ks & 1) * 32;
        if (eg == 0) {
            if ((ks & 1) == 0) {
#pragma unroll
                for (int e = 0; e < 3; e++) {
                    float4 bev = __ldg((const float4*)&be[e*64 + f0]);
#pragma unroll
                    for (int r = 0; r < 4; r++) {
                        m[e][r][0] = pack2(bev.x,bev.y); m[e][r][1] = pack2(bev.z,bev.w);
                    }
                }
            } else {
#pragma unroll
                for (int e = 0; e < 3; e++)
#pragma unroll
                    for (int r = 0; r < 4; r++) m[e][r][0]=m[e][r][1]=0ull;
            }
            msg_core<3,0>(sm, rg, f0, dbase, m);
        } else {
            if ((ks & 1) == 0) {
#pragma unroll
                for (int e = 0; e < 2; e++) {
                    float4 bev = __ldg((const float4*)&be[(3+e)*64 + f0]);
#pragma unroll
                    for (int r = 0; r < 4; r++) {
                        m[e][r][0] = pack2(bev.x,bev.y); m[e][r][1] = pack2(bev.z,bev.w);
                    }
                }
            } else {
#pragma unroll
                for (int e = 0; e < 2; e++)
#pragma unroll
                    for (int r = 0; r < 4; r++) m[e][r][0]=m[e][r][1]=0ull;
            }
            msg_core<2,3>(sm, rg, f0, dbase, m);
        }
        if (ks == 1) scr_w(sm, OFF_SCR0, slot, m[0]);
        if (ks == 3) scr_w(sm, OFF_SCR1, slot, m[0]);
        __syncthreads();
        if (ks == 0) scr_a(sm, OFF_SCR0, slot, m[0]);
        if (ks == 2) scr_a(sm, OFF_SCR1, slot, m[0]);
        __syncthreads();
        if (ks == 1) scr_w(sm, OFF_SCR0, slot, m[1]);
        if (ks == 3) scr_w(sm, OFF_SCR1, slot, m[1]);
        __syncthreads();
        if (ks == 0) scr_a(sm, OFF_SCR0, slot, m[1]);
        if (ks == 2) scr_a(sm, OFF_SCR1, slot, m[1]);
        __syncthreads();
        if (ks == 1) scr_w(sm, OFF_SCR0, slot, m[2]);
        __syncthreads();
        if (ks == 0) {
            scr_a(sm, OFF_SCR0, slot, m[2]);
            msg_out<3,0>(sm, rg, f0, fg, r0, ba, m);
        }
        if (ks == 2) msg_out<2,3>(sm, rg, f0, fg, r0, ba, m);
        cluster_bar();

        // ================= PHASE 2: scores + merged =================
        for (int i = tid; i < 640; i += THREADS)
            sm[OFF_SROW + i] = __expf(-__ldcg(&g_rowg[b*640 + i]));
        for (int i = tid; i < 160; i += THREADS)
            sm[OFF_SCOL + i] = __expf(-__ldcg(&g_colba[(b*Nn + j0)*5 + i]));
        {
            __half* mh = (__half*)&sm[OFF_MASKH];
            for (int i = tid; i < 1024; i += THREADS) {
                int irow = i >> 3, seg = i & 7;
                int4 mv = __ldg((const int4*)&mask[(size_t)(b*Nn + irow)*Nn + j0 + seg*4]);
                __half2 h01 = __floats2half2_rn((float)mv.x, (float)mv.y);
                __half2 h23 = __floats2half2_rn((float)mv.z, (float)mv.w);
                *(__half2*)&mh[irow*32 + seg*4]     = h01;
                *(__half2*)&mh[irow*32 + seg*4 + 2] = h23;
            }
        }
        __syncthreads();

        // scores: sigmoid(row+col) = 1/(1 + e^-row * e^-col); 1 MUFU each.
        const __half* mh = (const __half*)&sm[OFF_MASKH];
        float* outB = out + (size_t)(t*Bb + b)*(Nn*Nn*Ee) + (size_t)j0*Ee;
#pragma unroll 2
        for (int p = 0; p < 10; p++) {
            int idx4 = p*512 + tid;
            int i = idx4 / 40;
            int posb = (idx4 - i*40) * 4;
            float4 ecol = *(const float4*)&sm[OFF_SCOL + posb];
            const float* ecp = (const float*)&ecol;
            float4 sv;
            float* svp = (float*)&sv;
#pragma unroll
            for (int u = 0; u < 4; u++) {
                int pos = posb + u;
                int j = (pos * 6554) >> 15;
                int e = pos - j*5;
                float er = sm[OFF_SROW + i*5 + e];
                float mval = __half2float(mh[i*32 + j]);
                float s = mval * __fdividef(1.0f, fmaf(er, ecp[u], 1.0f));
                svp[u] = s;
                sm[OFF_SSC + i*180 + e*36 + j] = s;
            }
            *(float4*)&outB[(size_t)i*640 + posb] = sv;
        }

        if (t < T_ITERS - 1) {
            __syncthreads();
            const int td = tid & 7;
            const int ti = (tid >> 3) & 31;
            const int kh = tid >> 8;
            const int d0 = td * 8;
            u64 a2[4][4];
#pragma unroll
            for (int q = 0; q < 4; q++)
#pragma unroll
                for (int h = 0; h < 4; h++) a2[q][h] = 0ull;

#pragma unroll 1
            for (int jq = 0; jq < 4; jq++) {
                const int jbase = kh*16 + jq*4;
#pragma unroll
                for (int e = 0; e < 5; e++) {
                    float4 sq[4];
#pragma unroll
                    for (int q = 0; q < 4; q++)
                        sq[q] = *(const float4*)&sm[OFF_SSC + (ti*4+q)*180 + e*36 + jbase];
#pragma unroll
                    for (int jj = 0; jj < 4; jj++) {
                        const float* mr = &sm[OFF_MSG + (jbase+jj)*320 + e*64 + td*4];
                        float4 ma = *(const float4*)mr;
                        float4 mb = *(const float4*)(mr + 32);
                        u64 m0 = pack2(ma.x,ma.y), m1 = pack2(ma.z,ma.w);
                        u64 m2 = pack2(mb.x,mb.y), m3 = pack2(mb.z,mb.w);
#pragma unroll
                        for (int q = 0; q < 4; q++) {
                            float s = ((const float*)&sq[q])[jj];
                            u64 ss = pack2(s,s);
                            a2[q][0] = fma2(ss, m0, a2[q][0]);
                            a2[q][1] = fma2(ss, m1, a2[q][1]);
                            a2[q][2] = fma2(ss, m2, a2[q][2]);
                            a2[q][3] = fma2(ss, m3, a2[q][3]);
                        }
                    }
                }
            }
#pragma unroll
            for (int q = 0; q < 4; q++) {
                float v[8];
                unpack2(a2[q][0], v[0], v[1]); unpack2(a2[q][1], v[2], v[3]);
                unpack2(a2[q][2], v[4], v[5]); unpack2(a2[q][3], v[6], v[7]);
                float* dst = &g_part[js*2 + kh][b*Nn + ti*4 + q][d0];
                *(float4*)dst       = make_float4(v[0],v[1],v[2],v[3]);
                *(float4*)(dst + 4) = make_float4(v[4],v[5],v[6],v[7]);
            }
            cluster_bar();
        }
    }
}

extern "C" void kernel_launch(void* const* d_in, const int* in_sizes, int n_in,
                              void* d_out, int out_size) {
    const float* inputs = (const float*)d_in[0];
    const int*   mask   = (const int*)  d_in[1];
    const float* We     = (const float*)d_in[2];
    const float* be     = (const float*)d_in[3];
    const float* Wa     = (const float*)d_in[4];
    const float* ba     = (const float*)d_in[5];
    const float* Wr     = (const float*)d_in[6];
    const float* br     = (const float*)d_in[7];
    const float* Wz     = (const float*)d_in[8];
    const float* bz     = (const float*)d_in[9];
    const float* Wh     = (const float*)d_in[10];
    const float* bh     = (const float*)d_in[11];
    float* out = (float*)d_out;

    static int configured = 0;
    if (!configured) {
        cudaFuncSetAttribute(grrn, cudaFuncAttributeMaxDynamicSharedMemorySize,
                             SMEM_FLOATS * 4);
        configured = 1;
    }
    grrn<<<GRID, THREADS, SMEM_FLOATS * 4>>>(inputs, mask, We, be, Wa, ba,
                                             Wr, br, Wz, bz, Wh, bh, out);
}